// round 15
// baseline (speedup 1.0000x reference)
#include <cuda_runtime.h>
#include <cuda_bf16.h>

#define S_LEN   2048
#define D_MODEL 1024
#define NH      16
#define DK      64
#define BATCH   2
#define M_ROWS  (BATCH * S_LEN)   // 4096
#define AELEMS  ((size_t)M_ROWS * D_MODEL)   // 4194304
#define WELEMS  ((size_t)D_MODEL * D_MODEL)  // 1048576

// Scratch (allocation-free rule: __device__ globals), all bf16 hi/lo pairs
__device__ __nv_bfloat16 g_axh[3 * AELEMS], g_axl[3 * AELEMS];  // split q/k/v inputs
__device__ __nv_bfloat16 g_wh [4 * WELEMS], g_wl [4 * WELEMS];  // split weights
__device__ __nv_bfloat16 g_qh[AELEMS], g_ql[AELEMS];            // (b,h,s,d)
__device__ __nv_bfloat16 g_kh[AELEMS], g_kl[AELEMS];
__device__ __nv_bfloat16 g_vh[AELEMS], g_vl[AELEMS];
__device__ __nv_bfloat16 g_aoh[AELEMS], g_aol[AELEMS];          // attn out (b,s,D)

// ---------------------------------------------------------------------------
// Helpers
// ---------------------------------------------------------------------------
__device__ __forceinline__ void ldsm_x4(unsigned* r, unsigned addr) {
    asm volatile("ldmatrix.sync.aligned.m8n8.x4.shared.b16 {%0,%1,%2,%3}, [%4];\n"
        : "=r"(r[0]), "=r"(r[1]), "=r"(r[2]), "=r"(r[3]) : "r"(addr));
}
__device__ __forceinline__ void ldsm_x4t(unsigned* r, unsigned addr) {
    asm volatile("ldmatrix.sync.aligned.m8n8.x4.trans.shared.b16 {%0,%1,%2,%3}, [%4];\n"
        : "=r"(r[0]), "=r"(r[1]), "=r"(r[2]), "=r"(r[3]) : "r"(addr));
}
__device__ __forceinline__ void mma_bf16(float* c, const unsigned* a, const unsigned* b) {
    asm volatile(
        "mma.sync.aligned.m16n8k16.row.col.f32.bf16.bf16.f32 "
        "{%0,%1,%2,%3}, {%4,%5,%6,%7}, {%8,%9}, {%0,%1,%2,%3};\n"
        : "+f"(c[0]), "+f"(c[1]), "+f"(c[2]), "+f"(c[3])
        : "r"(a[0]), "r"(a[1]), "r"(a[2]), "r"(a[3]), "r"(b[0]), "r"(b[1]));
}
__device__ __forceinline__ void split2(float x, float y,
                                       __nv_bfloat162& h2, __nv_bfloat162& l2) {
    __nv_bfloat16 hx = __float2bfloat16(x);
    __nv_bfloat16 hy = __float2bfloat16(y);
    __nv_bfloat16 lx = __float2bfloat16(x - __bfloat162float(hx));
    __nv_bfloat16 ly = __float2bfloat16(y - __bfloat162float(hy));
    h2 = __halves2bfloat162(hx, hy);
    l2 = __halves2bfloat162(lx, ly);
}
#define CP16(saddr_, gptr_) \
    asm volatile("cp.async.cg.shared.global [%0], [%1], 16;\n" \
                 :: "r"(saddr_), "l"(gptr_))
#define CP_COMMIT() asm volatile("cp.async.commit_group;\n" ::: "memory")
#define CP_WAIT0()  asm volatile("cp.async.wait_group 0;\n" ::: "memory")
#define CP_WAIT1()  asm volatile("cp.async.wait_group 1;\n" ::: "memory")

// ---------------------------------------------------------------------------
// Pre-split: fp32 -> bf16 hi/lo. One launch for q/k/v, one for weights.
// ---------------------------------------------------------------------------
__global__ __launch_bounds__(256) void split3_kernel(
    const float* __restrict__ s0, const float* __restrict__ s1,
    const float* __restrict__ s2, int n4)
{
    const int z = blockIdx.y;
    const float* src = (z == 0) ? s0 : (z == 1) ? s1 : s2;
    __nv_bfloat16* hi = g_axh + (size_t)z * AELEMS;
    __nv_bfloat16* lo = g_axl + (size_t)z * AELEMS;
    int i = blockIdx.x * blockDim.x + threadIdx.x;
    if (i >= n4) return;
    float4 v = ((const float4*)src)[i];
    __nv_bfloat162 h2, l2;
    split2(v.x, v.y, h2, l2);
    *(__nv_bfloat162*)&hi[4 * i]     = h2;
    *(__nv_bfloat162*)&lo[4 * i]     = l2;
    split2(v.z, v.w, h2, l2);
    *(__nv_bfloat162*)&hi[4 * i + 2] = h2;
    *(__nv_bfloat162*)&lo[4 * i + 2] = l2;
}

__global__ __launch_bounds__(256) void wsplit4_kernel(
    const float* __restrict__ s0, const float* __restrict__ s1,
    const float* __restrict__ s2, const float* __restrict__ s3, int n4)
{
    const int z = blockIdx.y;
    const float* src = (z == 0) ? s0 : (z == 1) ? s1 : (z == 2) ? s2 : s3;
    __nv_bfloat16* hi = g_wh + (size_t)z * WELEMS;
    __nv_bfloat16* lo = g_wl + (size_t)z * WELEMS;
    int i = blockIdx.x * blockDim.x + threadIdx.x;
    if (i >= n4) return;
    float4 v = ((const float4*)src)[i];
    __nv_bfloat162 h2, l2;
    split2(v.x, v.y, h2, l2);
    *(__nv_bfloat162*)&hi[4 * i]     = h2;
    *(__nv_bfloat162*)&lo[4 * i]     = l2;
    split2(v.z, v.w, h2, l2);
    *(__nv_bfloat162*)&hi[4 * i + 2] = h2;
    *(__nv_bfloat162*)&lo[4 * i + 2] = l2;
}

// ---------------------------------------------------------------------------
// Tensor-core GEMM. All fragment LDSMs of an iteration hoisted before all
// MMAs (double-buffered in registers) so the scoreboard overlaps crossbar
// with tensor. 1 CTA/SM (no min-blocks cap) so frags stay in registers.
// Per-acc MMA order unchanged => bitwise-identical results.
// ---------------------------------------------------------------------------
#define BM 128
#define BN 128
#define BK 32
#define A_ROWB  80
#define W_ROWB  272
#define AHI_OFF 0
#define ALO_OFF 10240
#define WHI_OFF 20480
#define WLO_OFF 29184
#define BUF_BYTES 37888
#define GEMM_SMEM (2 * BUF_BYTES)   // 75776

__device__ __forceinline__ void gemm_mma_body(
    const __nv_bfloat16* __restrict__ Ahi, const __nv_bfloat16* __restrict__ Alo,
    const __nv_bfloat16* __restrict__ Whi, const __nv_bfloat16* __restrict__ Wlo,
    const float* __restrict__ bias,
    __nv_bfloat16* __restrict__ Chi, __nv_bfloat16* __restrict__ Clo,
    float* __restrict__ Cf, int split_heads, int bm, int bn, char* smem)
{
    const int tid  = threadIdx.x;
    const int lane = tid & 31;
    const int wid  = tid >> 5;
    const int warp_m = wid & 1;
    const int warp_n = wid >> 1;

    const unsigned sbase = (unsigned)__cvta_generic_to_shared(smem);

    const int l16 = lane & 15;
    const unsigned aLdOff = ((warp_m * 64 + l16) * A_ROWB + (lane >> 4) * 16);
    const unsigned wLdOff4 = (l16 * W_ROWB + (lane >> 4) * 16 + warp_n * 64);

    const int aRow0 = tid >> 2,  aCi = (tid & 3);
    const int wRow0 = tid >> 4,  wCi = (tid & 15);

    float acc[4][4][4];
#pragma unroll
    for (int i = 0; i < 4; i++)
#pragma unroll
        for (int j = 0; j < 4; j++)
#pragma unroll
            for (int r = 0; r < 4; r++) acc[i][j][r] = 0.f;

#define ISSUE_TILES(buf_, k0_)                                                   \
    {                                                                            \
        const unsigned sb = sbase + (buf_) * BUF_BYTES;                          \
        _Pragma("unroll")                                                        \
        for (int j = 0; j < 2; j++) {                                            \
            const int row = aRow0 + j * 64;                                      \
            const size_t g = (size_t)(bm + row) * D_MODEL + (k0_) + aCi * 8;     \
            CP16(sb + AHI_OFF + row * A_ROWB + aCi * 16, Ahi + g);               \
            CP16(sb + ALO_OFF + row * A_ROWB + aCi * 16, Alo + g);               \
        }                                                                        \
        _Pragma("unroll")                                                        \
        for (int j = 0; j < 2; j++) {                                            \
            const int row = wRow0 + j * 16;                                      \
            const size_t g = (size_t)((k0_) + row) * D_MODEL + bn + wCi * 8;     \
            CP16(sb + WHI_OFF + row * W_ROWB + wCi * 16, Whi + g);               \
            CP16(sb + WLO_OFF + row * W_ROWB + wCi * 16, Wlo + g);               \
        }                                                                        \
    }

    ISSUE_TILES(0, 0);
    CP_COMMIT();
    CP_WAIT0();
    __syncthreads();

    const int NIT = D_MODEL / BK;   // 32
    for (int it = 0; it < NIT; it++) {
        if (it + 1 < NIT) {
            ISSUE_TILES((it + 1) & 1, (it + 1) * BK);
            CP_COMMIT();
        }

        const unsigned bufB = sbase + (unsigned)((it & 1) * BUF_BYTES);

        // ---- hoist ALL fragment loads of this iteration ----
        unsigned bh[2][4][2], bl[2][4][2];
        unsigned ah[2][4][4], al[2][4][4];
#pragma unroll
        for (int ks = 0; ks < 2; ks++) {
#pragma unroll
            for (int nt2 = 0; nt2 < 2; nt2++) {
                unsigned r[4];
                unsigned woff = bufB + wLdOff4 + ks * 16 * W_ROWB + nt2 * 32;
                ldsm_x4t(r, woff + WHI_OFF);
                bh[ks][2 * nt2][0] = r[0]; bh[ks][2 * nt2][1] = r[1];
                bh[ks][2 * nt2 + 1][0] = r[2]; bh[ks][2 * nt2 + 1][1] = r[3];
                ldsm_x4t(r, woff + WLO_OFF);
                bl[ks][2 * nt2][0] = r[0]; bl[ks][2 * nt2][1] = r[1];
                bl[ks][2 * nt2 + 1][0] = r[2]; bl[ks][2 * nt2 + 1][1] = r[3];
            }
#pragma unroll
            for (int mt = 0; mt < 4; mt++) {
                unsigned aoff = bufB + aLdOff + mt * 16 * A_ROWB + ks * 32;
                ldsm_x4(ah[ks][mt], aoff + AHI_OFF);
                ldsm_x4(al[ks][mt], aoff + ALO_OFF);
            }
        }

        // ---- then ALL MMAs (per-acc order unchanged) ----
#pragma unroll
        for (int ks = 0; ks < 2; ks++) {
#pragma unroll
            for (int mt = 0; mt < 4; mt++) {
#pragma unroll
                for (int nt = 0; nt < 4; nt++) mma_bf16(acc[mt][nt], ah[ks][mt], bh[ks][nt]);
#pragma unroll
                for (int nt = 0; nt < 4; nt++) mma_bf16(acc[mt][nt], ah[ks][mt], bl[ks][nt]);
#pragma unroll
                for (int nt = 0; nt < 4; nt++) mma_bf16(acc[mt][nt], al[ks][mt], bh[ks][nt]);
            }
        }

        if (it + 1 < NIT) CP_WAIT0();
        __syncthreads();
    }
#undef ISSUE_TILES

    const int crow = lane >> 2;
    const int ccol = (lane & 3) << 1;
#pragma unroll
    for (int nt = 0; nt < 4; nt++) {
        const int colb = warp_n * 32 + nt * 8 + ccol;
        const float bv0 = bias[bn + colb];
        const float bv1 = bias[bn + colb + 1];
#pragma unroll
        for (int mt = 0; mt < 4; mt++) {
#pragma unroll
            for (int half = 0; half < 2; half++) {
                const int rowb = warp_m * 64 + mt * 16 + crow + half * 8;
                const int gr   = bm + rowb;
                const float vx = acc[mt][nt][half * 2 + 0] + bv0;
                const float vy = acc[mt][nt][half * 2 + 1] + bv1;
                if (split_heads) {
                    const int gcol = bn + colb;
                    const int h  = gcol >> 6;
                    const int d0 = gcol & 63;
                    const int bb = gr >> 11;
                    const int ss = gr & (S_LEN - 1);
                    const size_t e = (((size_t)(bb * NH + h) * S_LEN + ss) * DK + d0);
                    __nv_bfloat162 h2, l2;
                    split2(vx, vy, h2, l2);
                    *(__nv_bfloat162*)&Chi[e] = h2;
                    *(__nv_bfloat162*)&Clo[e] = l2;
                } else {
                    float2 v; v.x = vx; v.y = vy;
                    *(float2*)&Cf[(size_t)gr * D_MODEL + colb + bn] = v;
                }
            }
        }
    }
}

__global__ __launch_bounds__(256) void qkv_gemm_kernel2(
    const float* __restrict__ b_q, const float* __restrict__ b_k,
    const float* __restrict__ b_v)
{
    extern __shared__ char smem[];
    const int z = blockIdx.z;
    const __nv_bfloat16* Ahi = g_axh + (size_t)z * AELEMS;
    const __nv_bfloat16* Alo = g_axl + (size_t)z * AELEMS;
    const __nv_bfloat16* Whi = g_wh + (size_t)z * WELEMS;
    const __nv_bfloat16* Wlo = g_wl + (size_t)z * WELEMS;
    __nv_bfloat16* Chi = (z == 0) ? g_qh : (z == 1) ? g_kh : g_vh;
    __nv_bfloat16* Clo = (z == 0) ? g_ql : (z == 1) ? g_kl : g_vl;
    const float* bias = (z == 0) ? b_q : (z == 1) ? b_k : b_v;
    gemm_mma_body(Ahi, Alo, Whi, Wlo, bias,
                  Chi, Clo, nullptr, 1, blockIdx.y * BM, blockIdx.x * BN, smem);
}

__global__ __launch_bounds__(256) void out_gemm_kernel(
    const float* __restrict__ bias, float* __restrict__ C)
{
    extern __shared__ char smem[];
    gemm_mma_body(g_aoh, g_aol, g_wh + 3 * WELEMS, g_wl + 3 * WELEMS, bias,
                  nullptr, nullptr, C, 0, blockIdx.y * BM, blockIdx.x * BN, smem);
}

// ---------------------------------------------------------------------------
// Tensor-core flash attention (unchanged from R14 passing version)
// ---------------------------------------------------------------------------
#define AT_ROWB 144
#define KHI_B   0
#define KLO_B   9216
#define VHI_B   18432
#define VLO_B   27648
#define PM_B    36864
#define AT_BUF  37120
#define AT_SMEM (2 * AT_BUF)
#define QHI_B   0
#define QLO_B   18432

__global__ __launch_bounds__(256) void attn_mma_kernel(
    const float* __restrict__ pmask)
{
    extern __shared__ char sm[];
    const unsigned sbase = (unsigned)__cvta_generic_to_shared(sm);

    const int qt = (int)(gridDim.x - 1 - blockIdx.x);
    const int h  = blockIdx.y;
    const int b  = blockIdx.z;
    const int q0 = qt * 128;

    const int tid  = threadIdx.x;
    const int lane = tid & 31;
    const int wid  = tid >> 5;
    const int l16  = lane & 15;

    const size_t headoff = (size_t)(b * NH + h) * S_LEN * DK;
    const __nv_bfloat16* Qh = g_qh + headoff;
    const __nv_bfloat16* Ql = g_ql + headoff;
    const __nv_bfloat16* Kh = g_kh + headoff;
    const __nv_bfloat16* Kl = g_kl + headoff;
    const __nv_bfloat16* Vh = g_vh + headoff;
    const __nv_bfloat16* Vl = g_vl + headoff;

    // ---- Q phase ----
    {
#pragma unroll
        for (int j = 0; j < 4; j++) {
            const int c   = tid + j * 256;
            const int row = c >> 3;
            const int ci  = c & 7;
            const size_t g = (size_t)(q0 + row) * DK + ci * 8;
            CP16(sbase + QHI_B + row * AT_ROWB + ci * 16, Qh + g);
            CP16(sbase + QLO_B + row * AT_ROWB + ci * 16, Ql + g);
        }
        CP_COMMIT();
        CP_WAIT0();
        __syncthreads();
    }

    unsigned qh[4][4], ql[4][4];
    {
        const unsigned aLd = sbase + (wid * 16 + l16) * AT_ROWB + (lane >> 4) * 16;
#pragma unroll
        for (int ks = 0; ks < 4; ks++) {
            ldsm_x4(qh[ks], aLd + QHI_B + ks * 32);
            ldsm_x4(ql[ks], aLd + QLO_B + ks * 32);
        }
    }
    __syncthreads();

    float o[8][4];
#pragma unroll
    for (int nt = 0; nt < 8; nt++)
#pragma unroll
        for (int c = 0; c < 4; c++) o[nt][c] = 0.f;
    float m0 = -1e30f, m1 = -1e30f, l0 = 0.f, l1 = 0.f;
    float sfE[8][4], sfO[8][4];

    const int qg0 = q0 + wid * 16;
    const int rA  = lane >> 2;
    const int cA  = (lane & 3) << 1;

    const unsigned kLane4 = ((lane & 7) * AT_ROWB + ((lane >> 3) & 1) * 16
                            + (lane >> 4) * 8 * AT_ROWB);
    const unsigned vLane4 = (l16 * AT_ROWB + (lane >> 4) * 16);

    const int n_tiles = 2 * qt + 2;   // always even

    const int kvRow0 = tid >> 3;
    const int kvCi   = tid & 7;
    float pmReg = 0.f;

#define ISSUE_K(kt_, buf_)                                                       \
    {                                                                            \
        const int kk0 = (kt_) * 64;                                              \
        const unsigned sbuf = sbase + (buf_) * AT_BUF;                           \
        _Pragma("unroll")                                                        \
        for (int j = 0; j < 2; j++) {                                            \
            const int row = kvRow0 + j * 32;                                     \
            const size_t g = (size_t)(kk0 + row) * DK + kvCi * 8;                \
            const unsigned so = sbuf + row * AT_ROWB + kvCi * 16;                \
            CP16(so + KHI_B, Kh + g);                                            \
            CP16(so + KLO_B, Kl + g);                                            \
        }                                                                        \
        if (tid < 64) pmReg = pmask[b * S_LEN + kk0 + tid];                      \
    }

#define ISSUE_V(kt_, buf_)                                                       \
    {                                                                            \
        const int kk0 = (kt_) * 64;                                              \
        const unsigned sbuf = sbase + (buf_) * AT_BUF;                           \
        _Pragma("unroll")                                                        \
        for (int j = 0; j < 2; j++) {                                            \
            const int row = kvRow0 + j * 32;                                     \
            const size_t g = (size_t)(kk0 + row) * DK + kvCi * 8;                \
            const unsigned so = sbuf + row * AT_ROWB + kvCi * 16;                \
            CP16(so + VHI_B, Vh + g);                                            \
            CP16(so + VLO_B, Vl + g);                                            \
        }                                                                        \
        if (tid < 64) *(float*)(sm + (buf_) * AT_BUF + PM_B + tid * 4) = pmReg;  \
    }

#define S_MMAS(SFC, bufB_)                                                       \
    {                                                                            \
        _Pragma("unroll")                                                        \
        for (int nt = 0; nt < 8; nt++)                                           \
            _Pragma("unroll")                                                    \
            for (int c = 0; c < 4; c++) SFC[nt][c] = 0.f;                        \
        _Pragma("unroll")                                                        \
        for (int ks = 0; ks < 4; ks++) {                                         \
            unsigned kbh[8][2], kbl[8][2];                                       \
            _Pragma("unroll")                                                    \
            for (int nt2 = 0; nt2 < 4; nt2++) {                                  \
                unsigned r[4];                                                   \
                const unsigned kOff = (bufB_) + kLane4                           \
                    + (unsigned)(nt2 * 16 * AT_ROWB) + ks * 32;                  \
                ldsm_x4(r, kOff + KHI_B);                                        \
                kbh[2 * nt2][0] = r[0]; kbh[2 * nt2][1] = r[1];                  \
                kbh[2 * nt2 + 1][0] = r[2]; kbh[2 * nt2 + 1][1] = r[3];          \
                ldsm_x4(r, kOff + KLO_B);                                        \
                kbl[2 * nt2][0] = r[0]; kbl[2 * nt2][1] = r[1];                  \
                kbl[2 * nt2 + 1][0] = r[2]; kbl[2 * nt2 + 1][1] = r[3];          \
            }                                                                    \
            _Pragma("unroll")                                                    \
            for (int nt = 0; nt < 8; nt++) mma_bf16(SFC[nt], qh[ks], kbh[nt]);   \
            _Pragma("unroll")                                                    \
            for (int nt = 0; nt < 8; nt++) mma_bf16(SFC[nt], qh[ks], kbl[nt]);   \
            _Pragma("unroll")                                                    \
            for (int nt = 0; nt < 8; nt++) mma_bf16(SFC[nt], ql[ks], kbh[nt]);   \
        }                                                                        \
    }

#define PV_MMAS(SFP, bufPB_)                                                     \
    {                                                                            \
        _Pragma("unroll")                                                        \
        for (int ks = 0; ks < 4; ks++) {                                         \
            unsigned ah[4], al[4];                                               \
            __nv_bfloat162 h2, l2;                                               \
            split2(SFP[2 * ks][0],     SFP[2 * ks][1],     h2, l2);              \
            ah[0] = *(unsigned*)&h2;  al[0] = *(unsigned*)&l2;                   \
            split2(SFP[2 * ks][2],     SFP[2 * ks][3],     h2, l2);              \
            ah[1] = *(unsigned*)&h2;  al[1] = *(unsigned*)&l2;                   \
            split2(SFP[2 * ks + 1][0], SFP[2 * ks + 1][1], h2, l2);              \
            ah[2] = *(unsigned*)&h2;  al[2] = *(unsigned*)&l2;                   \
            split2(SFP[2 * ks + 1][2], SFP[2 * ks + 1][3], h2, l2);              \
            ah[3] = *(unsigned*)&h2;  al[3] = *(unsigned*)&l2;                   \
            unsigned vbh[8][2], vbl[8][2];                                       \
            _Pragma("unroll")                                                    \
            for (int nt2 = 0; nt2 < 4; nt2++) {                                  \
                unsigned r[4];                                                   \
                const unsigned vOff = (bufPB_) + vLane4                          \
                    + (unsigned)(ks * 16 * AT_ROWB) + nt2 * 32;                  \
                ldsm_x4t(r, vOff + VHI_B);                                       \
                vbh[2 * nt2][0] = r[0]; vbh[2 * nt2][1] = r[1];                  \
                vbh[2 * nt2 + 1][0] = r[2]; vbh[2 * nt2 + 1][1] = r[3];          \
                ldsm_x4t(r, vOff + VLO_B);                                       \
                vbl[2 * nt2][0] = r[0]; vbl[2 * nt2][1] = r[1];                  \
                vbl[2 * nt2 + 1][0] = r[2]; vbl[2 * nt2 + 1][1] = r[3];          \
            }                                                                    \
            _Pragma("unroll")                                                    \
            for (int nt = 0; nt < 8; nt++) mma_bf16(o[nt], ah, vbh[nt]);         \
            _Pragma("unroll")                                                    \
            for (int nt = 0; nt < 8; nt++) mma_bf16(o[nt], ah, vbl[nt]);         \
            _Pragma("unroll")                                                    \
            for (int nt = 0; nt < 8; nt++) mma_bf16(o[nt], al, vbh[nt]);         \
        }                                                                        \
    }

#define SOFTMAX(SFC, k0_, bufB_)                                                 \
    {                                                                            \
        const float* pms = (const float*)(sm + ((bufB_) - sbase) + PM_B);        \
        const bool needmask = ((k0_) + 63 > qg0);                                \
        _Pragma("unroll")                                                        \
        for (int nt = 0; nt < 8; nt++) {                                         \
            _Pragma("unroll")                                                    \
            for (int c = 0; c < 4; c++) {                                        \
                const int kloc = nt * 8 + cA + (c & 1);                          \
                float v = SFC[nt][c] * 0.125f + pms[kloc];                       \
                if (needmask) {                                                  \
                    const int qg = qg0 + rA + (c >> 1) * 8;                      \
                    if ((k0_) + kloc > qg) v = -1e30f;                           \
                }                                                                \
                SFC[nt][c] = v;                                                  \
            }                                                                    \
        }                                                                        \
        float mt0 = -1e30f, mt1 = -1e30f;                                        \
        _Pragma("unroll")                                                        \
        for (int nt = 0; nt < 8; nt++) {                                         \
            mt0 = fmaxf(mt0, fmaxf(SFC[nt][0], SFC[nt][1]));                     \
            mt1 = fmaxf(mt1, fmaxf(SFC[nt][2], SFC[nt][3]));                     \
        }                                                                        \
        mt0 = fmaxf(mt0, __shfl_xor_sync(0xffffffffu, mt0, 1));                  \
        mt0 = fmaxf(mt0, __shfl_xor_sync(0xffffffffu, mt0, 2));                  \
        mt1 = fmaxf(mt1, __shfl_xor_sync(0xffffffffu, mt1, 1));                  \
        mt1 = fmaxf(mt1, __shfl_xor_sync(0xffffffffu, mt1, 2));                  \
        const float mn0 = fmaxf(m0, mt0);                                        \
        const float mn1 = fmaxf(m1, mt1);                                        \
        const float alpha0 = __expf(m0 - mn0);                                   \
        const float alpha1 = __expf(m1 - mn1);                                   \
        m0 = mn0; m1 = mn1;                                                      \
        float rs0 = 0.f, rs1 = 0.f;                                              \
        _Pragma("unroll")                                                        \
        for (int nt = 0; nt < 8; nt++) {                                         \
            SFC[nt][0] = __expf(SFC[nt][0] - mn0);                               \
            SFC[nt][1] = __expf(SFC[nt][1] - mn0);                               \
            SFC[nt][2] = __expf(SFC[nt][2] - mn1);                               \
            SFC[nt][3] = __expf(SFC[nt][3] - mn1);                               \
            rs0 += SFC[nt][0] + SFC[nt][1];                                      \
            rs1 += SFC[nt][2] + SFC[nt][3];                                      \
        }                                                                        \
        rs0 += __shfl_xor_sync(0xffffffffu, rs0, 1);                             \
        rs0 += __shfl_xor_sync(0xffffffffu, rs0, 2);                             \
        rs1 += __shfl_xor_sync(0xffffffffu, rs1, 1);                             \
        rs1 += __shfl_xor_sync(0xffffffffu, rs1, 2);                             \
        l0 = l0 * alpha0 + rs0;                                                  \
        l1 = l1 * alpha1 + rs1;                                                  \
        _Pragma("unroll")                                                        \
        for (int nt = 0; nt < 8; nt++) {                                         \
            o[nt][0] *= alpha0; o[nt][1] *= alpha0;                              \
            o[nt][2] *= alpha1; o[nt][3] *= alpha1;                              \
        }                                                                        \
    }

#define TILE_BODY(t_, BUF_, SFC, SFP, first_)                                    \
    {                                                                            \
        const int k0 = (t_) * 64;                                                \
        const unsigned bufB  = sbase + (BUF_) * AT_BUF;                          \
        const unsigned bufPB = sbase + (1 - (BUF_)) * AT_BUF;                    \
        if (!(first_)) CP_WAIT1();                                               \
        __syncthreads();                                                         \
        S_MMAS(SFC, bufB);                                                       \
        if ((t_) + 1 < n_tiles) { ISSUE_K((t_) + 1, 1 - (BUF_)); CP_COMMIT(); }  \
        if (!(first_)) PV_MMAS(SFP, bufPB);                                      \
        SOFTMAX(SFC, k0, bufB);                                                  \
        __syncthreads();                                                         \
        if ((t_) + 1 < n_tiles) { ISSUE_V((t_) + 1, 1 - (BUF_)); CP_COMMIT(); }  \
    }

    // prologue: full KV(0) into buf0
    ISSUE_K(0, 0);
    ISSUE_V(0, 0);
    CP_COMMIT();
    CP_WAIT0();

    for (int kt2 = 0; kt2 < n_tiles; kt2 += 2) {
        TILE_BODY(kt2,     0, sfE, sfO, (kt2 == 0));
        TILE_BODY(kt2 + 1, 1, sfO, sfE, false);
    }

    // epilogue: PV(n-1); its scores are in sfO (last tile is odd), V in buf1
    CP_WAIT0();
    __syncthreads();
    PV_MMAS(sfO, sbase + AT_BUF);

#undef ISSUE_K
#undef ISSUE_V
#undef S_MMAS
#undef PV_MMAS
#undef SOFTMAX
#undef TILE_BODY

    const float inv0 = 1.0f / l0;
    const float inv1 = 1.0f / l1;
#pragma unroll
    for (int nt = 0; nt < 8; nt++) {
        const int dcol = nt * 8 + cA;
        {
            const int qg = qg0 + rA;
            const size_t e = (size_t)(b * S_LEN + qg) * D_MODEL + h * DK + dcol;
            __nv_bfloat162 h2, l2;
            split2(o[nt][0] * inv0, o[nt][1] * inv0, h2, l2);
            *(__nv_bfloat162*)&g_aoh[e] = h2;
            *(__nv_bfloat162*)&g_aol[e] = l2;
        }
        {
            const int qg = qg0 + rA + 8;
            const size_t e = (size_t)(b * S_LEN + qg) * D_MODEL + h * DK + dcol;
            __nv_bfloat162 h2, l2;
            split2(o[nt][2] * inv1, o[nt][3] * inv1, h2, l2);
            *(__nv_bfloat162*)&g_aoh[e] = h2;
            *(__nv_bfloat162*)&g_aol[e] = l2;
        }
    }
}

// ---------------------------------------------------------------------------
extern "C" void kernel_launch(void* const* d_in, const int* in_sizes, int n_in,
                              void* d_out, int out_size)
{
    (void)in_sizes; (void)n_in; (void)out_size;
    const float* query = (const float*)d_in[0];
    const float* key   = (const float*)d_in[1];
    const float* value = (const float*)d_in[2];
    const float* pmask = (const float*)d_in[3];
    // d_in[4] lookahead_mask: causal structure applied analytically
    const float* w_q = (const float*)d_in[5];
    const float* w_k = (const float*)d_in[6];
    const float* w_v = (const float*)d_in[7];
    const float* w_o = (const float*)d_in[8];
    const float* b_q = (const float*)d_in[9];
    const float* b_k = (const float*)d_in[10];
    const float* b_v = (const float*)d_in[11];
    const float* b_o = (const float*)d_in[12];

    cudaFuncSetAttribute(qkv_gemm_kernel2, cudaFuncAttributeMaxDynamicSharedMemorySize,
                         GEMM_SMEM);
    cudaFuncSetAttribute(out_gemm_kernel, cudaFuncAttributeMaxDynamicSharedMemorySize,
                         GEMM_SMEM);
    cudaFuncSetAttribute(attn_mma_kernel, cudaFuncAttributeMaxDynamicSharedMemorySize,
                         AT_SMEM);

    const int WG4 = (int)(WELEMS / 4), AG4 = (int)(AELEMS / 4);
    dim3 sa_grid((AG4 + 255) / 256, 3);
    split3_kernel<<<sa_grid, 256>>>(query, key, value, AG4);
    dim3 sw_grid((WG4 + 255) / 256, 4);
    wsplit4_kernel<<<sw_grid, 256>>>(w_q, w_k, w_v, w_o, WG4);

    dim3 qkv_grid(D_MODEL / BN, M_ROWS / BM, 3);     // (8, 32, 3)
    qkv_gemm_kernel2<<<qkv_grid, 256, GEMM_SMEM>>>(b_q, b_k, b_v);

    dim3 agrid(S_LEN / 128, NH, BATCH);              // (16, 16, 2)
    attn_mma_kernel<<<agrid, 256, AT_SMEM>>>(pmask);

    dim3 ogrid(D_MODEL / BN, M_ROWS / BM);           // (8, 32)
    out_gemm_kernel<<<ogrid, 256, GEMM_SMEM>>>(b_o, (float*)d_out);
}

// round 16
// speedup vs baseline: 1.0415x; 1.0415x over previous
#include <cuda_runtime.h>
#include <cuda_bf16.h>

#define S_LEN   2048
#define D_MODEL 1024
#define NH      16
#define DK      64
#define BATCH   2
#define M_ROWS  (BATCH * S_LEN)   // 4096
#define AELEMS  ((size_t)M_ROWS * D_MODEL)   // 4194304
#define WELEMS  ((size_t)D_MODEL * D_MODEL)  // 1048576

// Scratch (allocation-free rule: __device__ globals), all bf16 hi/lo pairs
__device__ __nv_bfloat16 g_axh[3 * AELEMS], g_axl[3 * AELEMS];  // split q/k/v inputs
__device__ __nv_bfloat16 g_wh [4 * WELEMS], g_wl [4 * WELEMS];  // split weights
__device__ __nv_bfloat16 g_qh[AELEMS], g_ql[AELEMS];            // (b,h,s,d)
__device__ __nv_bfloat16 g_kh[AELEMS], g_kl[AELEMS];
__device__ __nv_bfloat16 g_vh[AELEMS], g_vl[AELEMS];
__device__ __nv_bfloat16 g_aoh[AELEMS], g_aol[AELEMS];          // attn out (b,s,D)

// ---------------------------------------------------------------------------
// Helpers
// ---------------------------------------------------------------------------
__device__ __forceinline__ void ldsm_x4(unsigned* r, unsigned addr) {
    asm volatile("ldmatrix.sync.aligned.m8n8.x4.shared.b16 {%0,%1,%2,%3}, [%4];\n"
        : "=r"(r[0]), "=r"(r[1]), "=r"(r[2]), "=r"(r[3]) : "r"(addr));
}
__device__ __forceinline__ void ldsm_x4t(unsigned* r, unsigned addr) {
    asm volatile("ldmatrix.sync.aligned.m8n8.x4.trans.shared.b16 {%0,%1,%2,%3}, [%4];\n"
        : "=r"(r[0]), "=r"(r[1]), "=r"(r[2]), "=r"(r[3]) : "r"(addr));
}
__device__ __forceinline__ void mma_bf16(float* c, const unsigned* a, const unsigned* b) {
    asm volatile(
        "mma.sync.aligned.m16n8k16.row.col.f32.bf16.bf16.f32 "
        "{%0,%1,%2,%3}, {%4,%5,%6,%7}, {%8,%9}, {%0,%1,%2,%3};\n"
        : "+f"(c[0]), "+f"(c[1]), "+f"(c[2]), "+f"(c[3])
        : "r"(a[0]), "r"(a[1]), "r"(a[2]), "r"(a[3]), "r"(b[0]), "r"(b[1]));
}
__device__ __forceinline__ void split2(float x, float y,
                                       __nv_bfloat162& h2, __nv_bfloat162& l2) {
    __nv_bfloat16 hx = __float2bfloat16(x);
    __nv_bfloat16 hy = __float2bfloat16(y);
    __nv_bfloat16 lx = __float2bfloat16(x - __bfloat162float(hx));
    __nv_bfloat16 ly = __float2bfloat16(y - __bfloat162float(hy));
    h2 = __halves2bfloat162(hx, hy);
    l2 = __halves2bfloat162(lx, ly);
}
#define CP16(saddr_, gptr_) \
    asm volatile("cp.async.cg.shared.global [%0], [%1], 16;\n" \
                 :: "r"(saddr_), "l"(gptr_))
#define CP_COMMIT() asm volatile("cp.async.commit_group;\n" ::: "memory")
#define CP_WAIT0()  asm volatile("cp.async.wait_group 0;\n" ::: "memory")
#define CP_WAIT1()  asm volatile("cp.async.wait_group 1;\n" ::: "memory")

// ---------------------------------------------------------------------------
// Pre-split: fp32 -> bf16 hi/lo. One launch for q/k/v, one for weights.
// ---------------------------------------------------------------------------
__global__ __launch_bounds__(256) void split3_kernel(
    const float* __restrict__ s0, const float* __restrict__ s1,
    const float* __restrict__ s2, int n4)
{
    const int z = blockIdx.y;
    const float* src = (z == 0) ? s0 : (z == 1) ? s1 : s2;
    __nv_bfloat16* hi = g_axh + (size_t)z * AELEMS;
    __nv_bfloat16* lo = g_axl + (size_t)z * AELEMS;
    int i = blockIdx.x * blockDim.x + threadIdx.x;
    if (i >= n4) return;
    float4 v = ((const float4*)src)[i];
    __nv_bfloat162 h2, l2;
    split2(v.x, v.y, h2, l2);
    *(__nv_bfloat162*)&hi[4 * i]     = h2;
    *(__nv_bfloat162*)&lo[4 * i]     = l2;
    split2(v.z, v.w, h2, l2);
    *(__nv_bfloat162*)&hi[4 * i + 2] = h2;
    *(__nv_bfloat162*)&lo[4 * i + 2] = l2;
}

__global__ __launch_bounds__(256) void wsplit4_kernel(
    const float* __restrict__ s0, const float* __restrict__ s1,
    const float* __restrict__ s2, const float* __restrict__ s3, int n4)
{
    const int z = blockIdx.y;
    const float* src = (z == 0) ? s0 : (z == 1) ? s1 : (z == 2) ? s2 : s3;
    __nv_bfloat16* hi = g_wh + (size_t)z * WELEMS;
    __nv_bfloat16* lo = g_wl + (size_t)z * WELEMS;
    int i = blockIdx.x * blockDim.x + threadIdx.x;
    if (i >= n4) return;
    float4 v = ((const float4*)src)[i];
    __nv_bfloat162 h2, l2;
    split2(v.x, v.y, h2, l2);
    *(__nv_bfloat162*)&hi[4 * i]     = h2;
    *(__nv_bfloat162*)&lo[4 * i]     = l2;
    split2(v.z, v.w, h2, l2);
    *(__nv_bfloat162*)&hi[4 * i + 2] = h2;
    *(__nv_bfloat162*)&lo[4 * i + 2] = l2;
}

// ---------------------------------------------------------------------------
// Tensor-core GEMM, pure bf16 via cp.async. 3-STAGE pipeline: tile t+2 issued
// at iter t; steady-state wait_group 1 => prefetch gets ~2 iterations to land
// (2-stage wait_group 0 exposed full DRAM latency every iteration).
// Fragment loads per-ks (R14 structure). Per-acc MMA order unchanged.
// ---------------------------------------------------------------------------
#define BM 128
#define BN 128
#define BK 32
#define A_ROWB  80
#define W_ROWB  272
#define AHI_OFF 0
#define ALO_OFF 10240
#define WHI_OFF 20480
#define WLO_OFF 29184
#define BUF_BYTES 37888
#define GEMM_SMEM (3 * BUF_BYTES)   // 113664

__device__ __forceinline__ void gemm_mma_body(
    const __nv_bfloat16* __restrict__ Ahi, const __nv_bfloat16* __restrict__ Alo,
    const __nv_bfloat16* __restrict__ Whi, const __nv_bfloat16* __restrict__ Wlo,
    const float* __restrict__ bias,
    __nv_bfloat16* __restrict__ Chi, __nv_bfloat16* __restrict__ Clo,
    float* __restrict__ Cf, int split_heads, int bm, int bn, char* smem)
{
    const int tid  = threadIdx.x;
    const int lane = tid & 31;
    const int wid  = tid >> 5;
    const int warp_m = wid & 1;
    const int warp_n = wid >> 1;

    const unsigned sbase = (unsigned)__cvta_generic_to_shared(smem);

    const int l16 = lane & 15;
    const unsigned aLdOff = ((warp_m * 64 + l16) * A_ROWB + (lane >> 4) * 16);
    const unsigned wLdOff4 = (l16 * W_ROWB + (lane >> 4) * 16 + warp_n * 64);

    const int aRow0 = tid >> 2,  aCi = (tid & 3);
    const int wRow0 = tid >> 4,  wCi = (tid & 15);

    float acc[4][4][4];
#pragma unroll
    for (int i = 0; i < 4; i++)
#pragma unroll
        for (int j = 0; j < 4; j++)
#pragma unroll
            for (int r = 0; r < 4; r++) acc[i][j][r] = 0.f;

#define ISSUE_TILES(buf_, k0_)                                                   \
    {                                                                            \
        const unsigned sb = sbase + (buf_) * BUF_BYTES;                          \
        _Pragma("unroll")                                                        \
        for (int j = 0; j < 2; j++) {                                            \
            const int row = aRow0 + j * 64;                                      \
            const size_t g = (size_t)(bm + row) * D_MODEL + (k0_) + aCi * 8;     \
            CP16(sb + AHI_OFF + row * A_ROWB + aCi * 16, Ahi + g);               \
            CP16(sb + ALO_OFF + row * A_ROWB + aCi * 16, Alo + g);               \
        }                                                                        \
        _Pragma("unroll")                                                        \
        for (int j = 0; j < 2; j++) {                                            \
            const int row = wRow0 + j * 16;                                      \
            const size_t g = (size_t)((k0_) + row) * D_MODEL + bn + wCi * 8;     \
            CP16(sb + WHI_OFF + row * W_ROWB + wCi * 16, Whi + g);               \
            CP16(sb + WLO_OFF + row * W_ROWB + wCi * 16, Wlo + g);               \
        }                                                                        \
    }

    // prologue: tiles 0 and 1 into bufs 0 and 1 (separate groups)
    ISSUE_TILES(0, 0);
    CP_COMMIT();
    ISSUE_TILES(1, BK);
    CP_COMMIT();

    const int NIT = D_MODEL / BK;   // 32
    int buf = 0;                    // buffer of tile `it`
    for (int it = 0; it < NIT; it++) {
        // need tile it complete; tile it+1's group may stay in flight
        if (it + 1 < NIT) CP_WAIT1(); else CP_WAIT0();
        __syncthreads();            // visibility of other threads' cp.async

        if (it + 2 < NIT) {
            const int nb = (buf + 2 >= 3) ? buf - 1 : buf + 2;   // (buf+2)%3
            ISSUE_TILES(nb, (it + 2) * BK);
            CP_COMMIT();
        }

        const unsigned bufB = sbase + (unsigned)(buf * BUF_BYTES);
#pragma unroll
        for (int ks = 0; ks < 2; ks++) {
            unsigned bh[4][2], bl[4][2];
#pragma unroll
            for (int nt2 = 0; nt2 < 2; nt2++) {
                unsigned r[4];
                unsigned woff = bufB + wLdOff4 + ks * 16 * W_ROWB + nt2 * 32;
                ldsm_x4t(r, woff + WHI_OFF);
                bh[2 * nt2][0] = r[0]; bh[2 * nt2][1] = r[1];
                bh[2 * nt2 + 1][0] = r[2]; bh[2 * nt2 + 1][1] = r[3];
                ldsm_x4t(r, woff + WLO_OFF);
                bl[2 * nt2][0] = r[0]; bl[2 * nt2][1] = r[1];
                bl[2 * nt2 + 1][0] = r[2]; bl[2 * nt2 + 1][1] = r[3];
            }
#pragma unroll
            for (int mt = 0; mt < 4; mt++) {
                unsigned ah[4], al[4];
                unsigned aoff = bufB + aLdOff + mt * 16 * A_ROWB + ks * 32;
                ldsm_x4(ah, aoff + AHI_OFF);
                ldsm_x4(al, aoff + ALO_OFF);
#pragma unroll
                for (int nt = 0; nt < 4; nt++) mma_bf16(acc[mt][nt], ah, bh[nt]);
#pragma unroll
                for (int nt = 0; nt < 4; nt++) mma_bf16(acc[mt][nt], ah, bl[nt]);
#pragma unroll
                for (int nt = 0; nt < 4; nt++) mma_bf16(acc[mt][nt], al, bh[nt]);
            }
        }

        buf = (buf + 1 >= 3) ? 0 : buf + 1;
    }
#undef ISSUE_TILES

    const int crow = lane >> 2;
    const int ccol = (lane & 3) << 1;
#pragma unroll
    for (int nt = 0; nt < 4; nt++) {
        const int colb = warp_n * 32 + nt * 8 + ccol;
        const float bv0 = bias[bn + colb];
        const float bv1 = bias[bn + colb + 1];
#pragma unroll
        for (int mt = 0; mt < 4; mt++) {
#pragma unroll
            for (int half = 0; half < 2; half++) {
                const int rowb = warp_m * 64 + mt * 16 + crow + half * 8;
                const int gr   = bm + rowb;
                const float vx = acc[mt][nt][half * 2 + 0] + bv0;
                const float vy = acc[mt][nt][half * 2 + 1] + bv1;
                if (split_heads) {
                    const int gcol = bn + colb;
                    const int h  = gcol >> 6;
                    const int d0 = gcol & 63;
                    const int bb = gr >> 11;
                    const int ss = gr & (S_LEN - 1);
                    const size_t e = (((size_t)(bb * NH + h) * S_LEN + ss) * DK + d0);
                    __nv_bfloat162 h2, l2;
                    split2(vx, vy, h2, l2);
                    *(__nv_bfloat162*)&Chi[e] = h2;
                    *(__nv_bfloat162*)&Clo[e] = l2;
                } else {
                    float2 v; v.x = vx; v.y = vy;
                    *(float2*)&Cf[(size_t)gr * D_MODEL + colb + bn] = v;
                }
            }
        }
    }
}

__global__ __launch_bounds__(256, 2) void qkv_gemm_kernel2(
    const float* __restrict__ b_q, const float* __restrict__ b_k,
    const float* __restrict__ b_v)
{
    extern __shared__ char smem[];
    const int z = blockIdx.z;
    const __nv_bfloat16* Ahi = g_axh + (size_t)z * AELEMS;
    const __nv_bfloat16* Alo = g_axl + (size_t)z * AELEMS;
    const __nv_bfloat16* Whi = g_wh + (size_t)z * WELEMS;
    const __nv_bfloat16* Wlo = g_wl + (size_t)z * WELEMS;
    __nv_bfloat16* Chi = (z == 0) ? g_qh : (z == 1) ? g_kh : g_vh;
    __nv_bfloat16* Clo = (z == 0) ? g_ql : (z == 1) ? g_kl : g_vl;
    const float* bias = (z == 0) ? b_q : (z == 1) ? b_k : b_v;
    gemm_mma_body(Ahi, Alo, Whi, Wlo, bias,
                  Chi, Clo, nullptr, 1, blockIdx.y * BM, blockIdx.x * BN, smem);
}

__global__ __launch_bounds__(256, 2) void out_gemm_kernel(
    const float* __restrict__ bias, float* __restrict__ C)
{
    extern __shared__ char smem[];
    gemm_mma_body(g_aoh, g_aol, g_wh + 3 * WELEMS, g_wl + 3 * WELEMS, bias,
                  nullptr, nullptr, C, 0, blockIdx.y * BM, blockIdx.x * BN, smem);
}

// ---------------------------------------------------------------------------
// Tensor-core flash attention (unchanged from R14 passing version)
// ---------------------------------------------------------------------------
#define AT_ROWB 144
#define KHI_B   0
#define KLO_B   9216
#define VHI_B   18432
#define VLO_B   27648
#define PM_B    36864
#define AT_BUF  37120
#define AT_SMEM (2 * AT_BUF)
#define QHI_B   0
#define QLO_B   18432

__global__ __launch_bounds__(256) void attn_mma_kernel(
    const float* __restrict__ pmask)
{
    extern __shared__ char sm[];
    const unsigned sbase = (unsigned)__cvta_generic_to_shared(sm);

    const int qt = (int)(gridDim.x - 1 - blockIdx.x);
    const int h  = blockIdx.y;
    const int b  = blockIdx.z;
    const int q0 = qt * 128;

    const int tid  = threadIdx.x;
    const int lane = tid & 31;
    const int wid  = tid >> 5;
    const int l16  = lane & 15;

    const size_t headoff = (size_t)(b * NH + h) * S_LEN * DK;
    const __nv_bfloat16* Qh = g_qh + headoff;
    const __nv_bfloat16* Ql = g_ql + headoff;
    const __nv_bfloat16* Kh = g_kh + headoff;
    const __nv_bfloat16* Kl = g_kl + headoff;
    const __nv_bfloat16* Vh = g_vh + headoff;
    const __nv_bfloat16* Vl = g_vl + headoff;

    // ---- Q phase ----
    {
#pragma unroll
        for (int j = 0; j < 4; j++) {
            const int c   = tid + j * 256;
            const int row = c >> 3;
            const int ci  = c & 7;
            const size_t g = (size_t)(q0 + row) * DK + ci * 8;
            CP16(sbase + QHI_B + row * AT_ROWB + ci * 16, Qh + g);
            CP16(sbase + QLO_B + row * AT_ROWB + ci * 16, Ql + g);
        }
        CP_COMMIT();
        CP_WAIT0();
        __syncthreads();
    }

    unsigned qh[4][4], ql[4][4];
    {
        const unsigned aLd = sbase + (wid * 16 + l16) * AT_ROWB + (lane >> 4) * 16;
#pragma unroll
        for (int ks = 0; ks < 4; ks++) {
            ldsm_x4(qh[ks], aLd + QHI_B + ks * 32);
            ldsm_x4(ql[ks], aLd + QLO_B + ks * 32);
        }
    }
    __syncthreads();

    float o[8][4];
#pragma unroll
    for (int nt = 0; nt < 8; nt++)
#pragma unroll
        for (int c = 0; c < 4; c++) o[nt][c] = 0.f;
    float m0 = -1e30f, m1 = -1e30f, l0 = 0.f, l1 = 0.f;
    float sfE[8][4], sfO[8][4];

    const int qg0 = q0 + wid * 16;
    const int rA  = lane >> 2;
    const int cA  = (lane & 3) << 1;

    const unsigned kLane4 = ((lane & 7) * AT_ROWB + ((lane >> 3) & 1) * 16
                            + (lane >> 4) * 8 * AT_ROWB);
    const unsigned vLane4 = (l16 * AT_ROWB + (lane >> 4) * 16);

    const int n_tiles = 2 * qt + 2;   // always even

    const int kvRow0 = tid >> 3;
    const int kvCi   = tid & 7;
    float pmReg = 0.f;

#define ISSUE_K(kt_, buf_)                                                       \
    {                                                                            \
        const int kk0 = (kt_) * 64;                                              \
        const unsigned sbuf = sbase + (buf_) * AT_BUF;                           \
        _Pragma("unroll")                                                        \
        for (int j = 0; j < 2; j++) {                                            \
            const int row = kvRow0 + j * 32;                                     \
            const size_t g = (size_t)(kk0 + row) * DK + kvCi * 8;                \
            const unsigned so = sbuf + row * AT_ROWB + kvCi * 16;                \
            CP16(so + KHI_B, Kh + g);                                            \
            CP16(so + KLO_B, Kl + g);                                            \
        }                                                                        \
        if (tid < 64) pmReg = pmask[b * S_LEN + kk0 + tid];                      \
    }

#define ISSUE_V(kt_, buf_)                                                       \
    {                                                                            \
        const int kk0 = (kt_) * 64;                                              \
        const unsigned sbuf = sbase + (buf_) * AT_BUF;                           \
        _Pragma("unroll")                                                        \
        for (int j = 0; j < 2; j++) {                                            \
            const int row = kvRow0 + j * 32;                                     \
            const size_t g = (size_t)(kk0 + row) * DK + kvCi * 8;                \
            const unsigned so = sbuf + row * AT_ROWB + kvCi * 16;                \
            CP16(so + VHI_B, Vh + g);                                            \
            CP16(so + VLO_B, Vl + g);                                            \
        }                                                                        \
        if (tid < 64) *(float*)(sm + (buf_) * AT_BUF + PM_B + tid * 4) = pmReg;  \
    }

#define S_MMAS(SFC, bufB_)                                                       \
    {                                                                            \
        _Pragma("unroll")                                                        \
        for (int nt = 0; nt < 8; nt++)                                           \
            _Pragma("unroll")                                                    \
            for (int c = 0; c < 4; c++) SFC[nt][c] = 0.f;                        \
        _Pragma("unroll")                                                        \
        for (int ks = 0; ks < 4; ks++) {                                         \
            unsigned kbh[8][2], kbl[8][2];                                       \
            _Pragma("unroll")                                                    \
            for (int nt2 = 0; nt2 < 4; nt2++) {                                  \
                unsigned r[4];                                                   \
                const unsigned kOff = (bufB_) + kLane4                           \
                    + (unsigned)(nt2 * 16 * AT_ROWB) + ks * 32;                  \
                ldsm_x4(r, kOff + KHI_B);                                        \
                kbh[2 * nt2][0] = r[0]; kbh[2 * nt2][1] = r[1];                  \
                kbh[2 * nt2 + 1][0] = r[2]; kbh[2 * nt2 + 1][1] = r[3];          \
                ldsm_x4(r, kOff + KLO_B);                                        \
                kbl[2 * nt2][0] = r[0]; kbl[2 * nt2][1] = r[1];                  \
                kbl[2 * nt2 + 1][0] = r[2]; kbl[2 * nt2 + 1][1] = r[3];          \
            }                                                                    \
            _Pragma("unroll")                                                    \
            for (int nt = 0; nt < 8; nt++) mma_bf16(SFC[nt], qh[ks], kbh[nt]);   \
            _Pragma("unroll")                                                    \
            for (int nt = 0; nt < 8; nt++) mma_bf16(SFC[nt], qh[ks], kbl[nt]);   \
            _Pragma("unroll")                                                    \
            for (int nt = 0; nt < 8; nt++) mma_bf16(SFC[nt], ql[ks], kbh[nt]);   \
        }                                                                        \
    }

#define PV_MMAS(SFP, bufPB_)                                                     \
    {                                                                            \
        _Pragma("unroll")                                                        \
        for (int ks = 0; ks < 4; ks++) {                                         \
            unsigned ah[4], al[4];                                               \
            __nv_bfloat162 h2, l2;                                               \
            split2(SFP[2 * ks][0],     SFP[2 * ks][1],     h2, l2);              \
            ah[0] = *(unsigned*)&h2;  al[0] = *(unsigned*)&l2;                   \
            split2(SFP[2 * ks][2],     SFP[2 * ks][3],     h2, l2);              \
            ah[1] = *(unsigned*)&h2;  al[1] = *(unsigned*)&l2;                   \
            split2(SFP[2 * ks + 1][0], SFP[2 * ks + 1][1], h2, l2);              \
            ah[2] = *(unsigned*)&h2;  al[2] = *(unsigned*)&l2;                   \
            split2(SFP[2 * ks + 1][2], SFP[2 * ks + 1][3], h2, l2);              \
            ah[3] = *(unsigned*)&h2;  al[3] = *(unsigned*)&l2;                   \
            unsigned vbh[8][2], vbl[8][2];                                       \
            _Pragma("unroll")                                                    \
            for (int nt2 = 0; nt2 < 4; nt2++) {                                  \
                unsigned r[4];                                                   \
                const unsigned vOff = (bufPB_) + vLane4                          \
                    + (unsigned)(ks * 16 * AT_ROWB) + nt2 * 32;                  \
                ldsm_x4t(r, vOff + VHI_B);                                       \
                vbh[2 * nt2][0] = r[0]; vbh[2 * nt2][1] = r[1];                  \
                vbh[2 * nt2 + 1][0] = r[2]; vbh[2 * nt2 + 1][1] = r[3];          \
                ldsm_x4t(r, vOff + VLO_B);                                       \
                vbl[2 * nt2][0] = r[0]; vbl[2 * nt2][1] = r[1];                  \
                vbl[2 * nt2 + 1][0] = r[2]; vbl[2 * nt2 + 1][1] = r[3];          \
            }                                                                    \
            _Pragma("unroll")                                                    \
            for (int nt = 0; nt < 8; nt++) mma_bf16(o[nt], ah, vbh[nt]);         \
            _Pragma("unroll")                                                    \
            for (int nt = 0; nt < 8; nt++) mma_bf16(o[nt], ah, vbl[nt]);         \
            _Pragma("unroll")                                                    \
            for (int nt = 0; nt < 8; nt++) mma_bf16(o[nt], al, vbh[nt]);         \
        }                                                                        \
    }

#define SOFTMAX(SFC, k0_, bufB_)                                                 \
    {                                                                            \
        const float* pms = (const float*)(sm + ((bufB_) - sbase) + PM_B);        \
        const bool needmask = ((k0_) + 63 > qg0);                                \
        _Pragma("unroll")                                                        \
        for (int nt = 0; nt < 8; nt++) {                                         \
            _Pragma("unroll")                                                    \
            for (int c = 0; c < 4; c++) {                                        \
                const int kloc = nt * 8 + cA + (c & 1);                          \
                float v = SFC[nt][c] * 0.125f + pms[kloc];                       \
                if (needmask) {                                                  \
                    const int qg = qg0 + rA + (c >> 1) * 8;                      \
                    if ((k0_) + kloc > qg) v = -1e30f;                           \
                }                                                                \
                SFC[nt][c] = v;                                                  \
            }                                                                    \
        }                                                                        \
        float mt0 = -1e30f, mt1 = -1e30f;                                        \
        _Pragma("unroll")                                                        \
        for (int nt = 0; nt < 8; nt++) {                                         \
            mt0 = fmaxf(mt0, fmaxf(SFC[nt][0], SFC[nt][1]));                     \
            mt1 = fmaxf(mt1, fmaxf(SFC[nt][2], SFC[nt][3]));                     \
        }                                                                        \
        mt0 = fmaxf(mt0, __shfl_xor_sync(0xffffffffu, mt0, 1));                  \
        mt0 = fmaxf(mt0, __shfl_xor_sync(0xffffffffu, mt0, 2));                  \
        mt1 = fmaxf(mt1, __shfl_xor_sync(0xffffffffu, mt1, 1));                  \
        mt1 = fmaxf(mt1, __shfl_xor_sync(0xffffffffu, mt1, 2));                  \
        const float mn0 = fmaxf(m0, mt0);                                        \
        const float mn1 = fmaxf(m1, mt1);                                        \
        const float alpha0 = __expf(m0 - mn0);                                   \
        const float alpha1 = __expf(m1 - mn1);                                   \
        m0 = mn0; m1 = mn1;                                                      \
        float rs0 = 0.f, rs1 = 0.f;                                              \
        _Pragma("unroll")                                                        \
        for (int nt = 0; nt < 8; nt++) {                                         \
            SFC[nt][0] = __expf(SFC[nt][0] - mn0);                               \
            SFC[nt][1] = __expf(SFC[nt][1] - mn0);                               \
            SFC[nt][2] = __expf(SFC[nt][2] - mn1);                               \
            SFC[nt][3] = __expf(SFC[nt][3] - mn1);                               \
            rs0 += SFC[nt][0] + SFC[nt][1];                                      \
            rs1 += SFC[nt][2] + SFC[nt][3];                                      \
        }                                                                        \
        rs0 += __shfl_xor_sync(0xffffffffu, rs0, 1);                             \
        rs0 += __shfl_xor_sync(0xffffffffu, rs0, 2);                             \
        rs1 += __shfl_xor_sync(0xffffffffu, rs1, 1);                             \
        rs1 += __shfl_xor_sync(0xffffffffu, rs1, 2);                             \
        l0 = l0 * alpha0 + rs0;                                                  \
        l1 = l1 * alpha1 + rs1;                                                  \
        _Pragma("unroll")                                                        \
        for (int nt = 0; nt < 8; nt++) {                                         \
            o[nt][0] *= alpha0; o[nt][1] *= alpha0;                              \
            o[nt][2] *= alpha1; o[nt][3] *= alpha1;                              \
        }                                                                        \
    }

#define TILE_BODY(t_, BUF_, SFC, SFP, first_)                                    \
    {                                                                            \
        const int k0 = (t_) * 64;                                                \
        const unsigned bufB  = sbase + (BUF_) * AT_BUF;                          \
        const unsigned bufPB = sbase + (1 - (BUF_)) * AT_BUF;                    \
        if (!(first_)) CP_WAIT1();                                               \
        __syncthreads();                                                         \
        S_MMAS(SFC, bufB);                                                       \
        if ((t_) + 1 < n_tiles) { ISSUE_K((t_) + 1, 1 - (BUF_)); CP_COMMIT(); }  \
        if (!(first_)) PV_MMAS(SFP, bufPB);                                      \
        SOFTMAX(SFC, k0, bufB);                                                  \
        __syncthreads();                                                         \
        if ((t_) + 1 < n_tiles) { ISSUE_V((t_) + 1, 1 - (BUF_)); CP_COMMIT(); }  \
    }

    // prologue: full KV(0) into buf0
    ISSUE_K(0, 0);
    ISSUE_V(0, 0);
    CP_COMMIT();
    CP_WAIT0();

    for (int kt2 = 0; kt2 < n_tiles; kt2 += 2) {
        TILE_BODY(kt2,     0, sfE, sfO, (kt2 == 0));
        TILE_BODY(kt2 + 1, 1, sfO, sfE, false);
    }

    // epilogue: PV(n-1); its scores are in sfO (last tile is odd), V in buf1
    CP_WAIT0();
    __syncthreads();
    PV_MMAS(sfO, sbase + AT_BUF);

#undef ISSUE_K
#undef ISSUE_V
#undef S_MMAS
#undef PV_MMAS
#undef SOFTMAX
#undef TILE_BODY

    const float inv0 = 1.0f / l0;
    const float inv1 = 1.0f / l1;
#pragma unroll
    for (int nt = 0; nt < 8; nt++) {
        const int dcol = nt * 8 + cA;
        {
            const int qg = qg0 + rA;
            const size_t e = (size_t)(b * S_LEN + qg) * D_MODEL + h * DK + dcol;
            __nv_bfloat162 h2, l2;
            split2(o[nt][0] * inv0, o[nt][1] * inv0, h2, l2);
            *(__nv_bfloat162*)&g_aoh[e] = h2;
            *(__nv_bfloat162*)&g_aol[e] = l2;
        }
        {
            const int qg = qg0 + rA + 8;
            const size_t e = (size_t)(b * S_LEN + qg) * D_MODEL + h * DK + dcol;
            __nv_bfloat162 h2, l2;
            split2(o[nt][2] * inv1, o[nt][3] * inv1, h2, l2);
            *(__nv_bfloat162*)&g_aoh[e] = h2;
            *(__nv_bfloat162*)&g_aol[e] = l2;
        }
    }
}

// ---------------------------------------------------------------------------
extern "C" void kernel_launch(void* const* d_in, const int* in_sizes, int n_in,
                              void* d_out, int out_size)
{
    (void)in_sizes; (void)n_in; (void)out_size;
    const float* query = (const float*)d_in[0];
    const float* key   = (const float*)d_in[1];
    const float* value = (const float*)d_in[2];
    const float* pmask = (const float*)d_in[3];
    // d_in[4] lookahead_mask: causal structure applied analytically
    const float* w_q = (const float*)d_in[5];
    const float* w_k = (const float*)d_in[6];
    const float* w_v = (const float*)d_in[7];
    const float* w_o = (const float*)d_in[8];
    const float* b_q = (const float*)d_in[9];
    const float* b_k = (const float*)d_in[10];
    const float* b_v = (const float*)d_in[11];
    const float* b_o = (const float*)d_in[12];

    cudaFuncSetAttribute(qkv_gemm_kernel2, cudaFuncAttributeMaxDynamicSharedMemorySize,
                         GEMM_SMEM);
    cudaFuncSetAttribute(out_gemm_kernel, cudaFuncAttributeMaxDynamicSharedMemorySize,
                         GEMM_SMEM);
    cudaFuncSetAttribute(attn_mma_kernel, cudaFuncAttributeMaxDynamicSharedMemorySize,
                         AT_SMEM);

    const int WG4 = (int)(WELEMS / 4), AG4 = (int)(AELEMS / 4);
    dim3 sa_grid((AG4 + 255) / 256, 3);
    split3_kernel<<<sa_grid, 256>>>(query, key, value, AG4);
    dim3 sw_grid((WG4 + 255) / 256, 4);
    wsplit4_kernel<<<sw_grid, 256>>>(w_q, w_k, w_v, w_o, WG4);

    dim3 qkv_grid(D_MODEL / BN, M_ROWS / BM, 3);     // (8, 32, 3)
    qkv_gemm_kernel2<<<qkv_grid, 256, GEMM_SMEM>>>(b_q, b_k, b_v);

    dim3 agrid(S_LEN / 128, NH, BATCH);              // (16, 16, 2)
    attn_mma_kernel<<<agrid, 256, AT_SMEM>>>(pmask);

    dim3 ogrid(D_MODEL / BN, M_ROWS / BM);           // (8, 32)
    out_gemm_kernel<<<ogrid, 256, GEMM_SMEM>>>(b_o, (float*)d_out);
}